// round 2
// baseline (speedup 1.0000x reference)
#include <cuda_runtime.h>
#include <math.h>

// Problem constants
constexpr int cB  = 256;
constexpr int cL  = 128;
constexpr int cH  = 512;
constexpr int cH4 = 2048;
constexpr int KCAT = 1040;   // 512 ctx + 512 h + 1 scalar + padding to mult of 16

// Persistent device scratch (static device globals: allocation-free)
__device__ float g_h[cB * cH];
__device__ float g_c[cB * cH];
__device__ float g_z[cB * cH4];
__device__ float g_q[cB * cH];
__device__ float g_enc_out[(size_t)cB * cL * cH];   // 67 MB
__device__ float g_enc_w1[(size_t)cB * cL * cH];    // 67 MB
__device__ float g_xcat[cB * KCAT];
__device__ float g_catW[(size_t)cH4 * KCAT];        // 8.5 MB
__device__ float g_decin[cL * cB];

// ---------------- math helpers (accurate-ish, MUFU-based) ----------------
__device__ __forceinline__ float fast_tanh(float x) {
    float a = fabsf(x);
    float e = __expf(-2.0f * a);            // e in (0,1], no overflow
    float r = __fdividef(1.0f - e, 1.0f + e);
    return copysignf(r, x);
}
__device__ __forceinline__ float fast_sig(float x) {
    return __fdividef(1.0f, 1.0f + __expf(-x));  // exp(-x)=inf -> 0, ok
}

// ---------------- prep: zero state, build catW / teacher inputs ----------------
__global__ void prep_kernel(const int* __restrict__ xs, const int* __restrict__ as,
                            const float* __restrict__ decWi, const float* __restrict__ decWh) {
    int stride = gridDim.x * blockDim.x;
    for (int idx = blockIdx.x * blockDim.x + threadIdx.x;
         idx < cH4 * KCAT; idx += stride) {
        if (idx < cB * cH) { g_h[idx] = 0.0f; g_c[idx] = 0.0f; }
        if (idx < cB * KCAT) g_xcat[idx] = 0.0f;
        if (idx < cL * cB) {
            int tt = idx / cB, bb = idx - tt * cB;
            g_decin[idx] = (tt == 0) ? 0.0f
                         : (float)xs[bb * cL + as[bb * cL + tt - 1]];
        }
        {
            int r = idx / KCAT, k = idx - r * KCAT;
            float v;
            if (k < cH)            v = decWi[r * (cH + 1) + k];          // ctx part
            else if (k < 2 * cH)   v = decWh[r * cH + (k - cH)];          // h part
            else if (k == 2 * cH)  v = decWi[r * (cH + 1) + cH];          // scalar in
            else                   v = 0.0f;                              // pad
            g_catW[idx] = v;
        }
    }
}

// ---------------- tiled fp32 GEMM: C[M,N] = A[M,K] * W[N,K]^T + bias ----------------
__global__ __launch_bounds__(256)
void gemm_abt(const float* __restrict__ A, const float* __restrict__ W,
              const float* __restrict__ bias, float* __restrict__ C,
              int M, int N, int K) {
    __shared__ float sA[64][17];
    __shared__ float sW[64][17];
    int tid = threadIdx.x;
    int tx = tid & 15;       // 16 col groups of 4
    int ty = tid >> 4;       // 16 row groups of 4
    int m0 = blockIdx.y * 64;
    int n0 = blockIdx.x * 64;

    float acc[4][4];
#pragma unroll
    for (int i = 0; i < 4; i++)
#pragma unroll
        for (int j = 0; j < 4; j++) acc[i][j] = 0.0f;

    for (int k0 = 0; k0 < K; k0 += 16) {
#pragma unroll
        for (int i = tid; i < 1024; i += 256) {
            int r = i >> 4, c = i & 15;
            sA[r][c] = A[(size_t)(m0 + r) * K + k0 + c];
            sW[r][c] = W[(size_t)(n0 + r) * K + k0 + c];
        }
        __syncthreads();
#pragma unroll
        for (int kk = 0; kk < 16; kk++) {
            float a[4], bv[4];
#pragma unroll
            for (int i = 0; i < 4; i++) a[i] = sA[ty * 4 + i][kk];
#pragma unroll
            for (int j = 0; j < 4; j++) bv[j] = sW[tx * 4 + j][kk];
#pragma unroll
            for (int i = 0; i < 4; i++)
#pragma unroll
                for (int j = 0; j < 4; j++)
                    acc[i][j] = fmaf(a[i], bv[j], acc[i][j]);
        }
        __syncthreads();
    }

#pragma unroll
    for (int i = 0; i < 4; i++) {
        int m = m0 + ty * 4 + i;
#pragma unroll
        for (int j = 0; j < 4; j++) {
            int n = n0 + tx * 4 + j;
            float v = acc[i][j];
            if (bias) v += bias[n];
            C[(size_t)m * N + n] = v;
        }
    }
}

// ---------------- LSTM gate update (enc: adds x*Wi term, writes enc_out) ----------------
__global__ __launch_bounds__(256)
void lstm_gates(const int* __restrict__ xs, const float* __restrict__ encWi,
                int t, int isEnc) {
    int idx = blockIdx.x * 256 + threadIdx.x;   // cB*cH threads
    int b = idx >> 9;
    int j = idx & (cH - 1);
    const float* zb = g_z + (size_t)b * cH4;
    float zi = zb[j];
    float zf = zb[cH + j];
    float zg = zb[2 * cH + j];
    float zo = zb[3 * cH + j];
    if (isEnc) {
        float xt = (float)xs[b * cL + t];
        zi = fmaf(xt, encWi[j], zi);
        zf = fmaf(xt, encWi[cH + j], zf);
        zg = fmaf(xt, encWi[2 * cH + j], zg);
        zo = fmaf(xt, encWi[3 * cH + j], zo);
    }
    float cn = fast_sig(zf) * g_c[idx] + fast_sig(zi) * fast_tanh(zg);
    float hn = fast_sig(zo) * fast_tanh(cn);
    g_c[idx] = cn;
    g_h[idx] = hn;
    if (isEnc) g_enc_out[(size_t)(b * cL + t) * cH + j] = hn;
}

// ---------------- fused attention: scores -> softmax/log_softmax -> context -> x_cat ----------------
__global__ __launch_bounds__(512)
void attn_fused(const float* __restrict__ vt_p, int t, float* __restrict__ out) {
    __shared__ float qs[cH];
    __shared__ float vts[cH];
    __shared__ float sc[cL];
    __shared__ float ajs[cL];
    __shared__ float redm[16];
    __shared__ float reds[16];

    int b = blockIdx.x;
    int tid = threadIdx.x;
    int warp = tid >> 5, lane = tid & 31;

    for (int i = tid; i < cH; i += 512) {
        qs[i]  = g_q[b * cH + i];
        vts[i] = vt_p[i];
    }
    __syncthreads();

    // scores[l] = sum_j vt[j] * tanh(enc_w1[b,l,j] + q[b,j])
    for (int l = warp; l < cL; l += 16) {
        const float* row = g_enc_w1 + (size_t)(b * cL + l) * cH;
        float s = 0.0f;
#pragma unroll 4
        for (int j = lane; j < cH; j += 32)
            s = fmaf(vts[j], fast_tanh(row[j] + qs[j]), s);
#pragma unroll
        for (int o = 16; o > 0; o >>= 1) s += __shfl_xor_sync(0xffffffffu, s, o);
        if (lane == 0) sc[l] = s;
    }
    __syncthreads();

    // block softmax over L=128 (all 512 threads participate; >=128 hold -inf/0)
    float sval = (tid < cL) ? sc[tid] : -3.0e38f;
    float m = sval;
#pragma unroll
    for (int o = 16; o > 0; o >>= 1) m = fmaxf(m, __shfl_xor_sync(0xffffffffu, m, o));
    if (lane == 0) redm[warp] = m;
    __syncthreads();
    if (tid < 16) {
        float mm = redm[tid];
#pragma unroll
        for (int o = 8; o > 0; o >>= 1) mm = fmaxf(mm, __shfl_xor_sync(0x0000ffffu, mm, o));
        if (tid == 0) redm[0] = mm;
    }
    __syncthreads();
    float mx = redm[0];

    float e = (tid < cL) ? __expf(sval - mx) : 0.0f;
    float ss = e;
#pragma unroll
    for (int o = 16; o > 0; o >>= 1) ss += __shfl_xor_sync(0xffffffffu, ss, o);
    if (lane == 0) reds[warp] = ss;
    __syncthreads();
    if (tid < 16) {
        float s2 = reds[tid];
#pragma unroll
        for (int o = 8; o > 0; o >>= 1) s2 += __shfl_xor_sync(0x0000ffffu, s2, o);
        if (tid == 0) reds[0] = s2;
    }
    __syncthreads();
    float tot = reds[0];

    if (tid < cL) {
        out[((size_t)b * cL + t) * cL + tid] = sval - mx - __logf(tot);
        ajs[tid] = __fdividef(e, tot);
    }
    __syncthreads();

    // context[j] = sum_l aj[l] * enc_out[b,l,j]; assemble x_cat = [ctx | h | dec_in]
    float acc = 0.0f;
    const float* eo = g_enc_out + (size_t)b * cL * cH + tid;
#pragma unroll 4
    for (int l = 0; l < cL; l++) acc = fmaf(ajs[l], eo[(size_t)l * cH], acc);

    g_xcat[b * KCAT + tid]      = acc;                  // context
    g_xcat[b * KCAT + cH + tid] = g_h[b * cH + tid];    // pre-update h
    if (tid == 0) g_xcat[b * KCAT + 2 * cH] = g_decin[t * cB + b];
}

// ---------------- host orchestration ----------------
extern "C" void kernel_launch(void* const* d_in, const int* in_sizes, int n_in,
                              void* d_out, int out_size) {
    const int*   xs      = (const int*)d_in[0];
    // d_in[1] = x_lens (unused by the math)
    const int*   argsort = (const int*)d_in[2];
    const float* enc_Wi  = (const float*)d_in[3];
    const float* enc_Wh  = (const float*)d_in[4];
    const float* enc_b   = (const float*)d_in[5];
    const float* dec_Wi  = (const float*)d_in[6];
    const float* dec_Wh  = (const float*)d_in[7];
    const float* dec_b   = (const float*)d_in[8];
    const float* w1      = (const float*)d_in[9];
    const float* w2      = (const float*)d_in[10];
    const float* vt      = (const float*)d_in[11];
    float*       out     = (float*)d_out;

    float *ph, *pz, *pq, *peo, *pew1, *pxcat, *pcatW;
    cudaGetSymbolAddress((void**)&ph,    g_h);
    cudaGetSymbolAddress((void**)&pz,    g_z);
    cudaGetSymbolAddress((void**)&pq,    g_q);
    cudaGetSymbolAddress((void**)&peo,   g_enc_out);
    cudaGetSymbolAddress((void**)&pew1,  g_enc_w1);
    cudaGetSymbolAddress((void**)&pxcat, g_xcat);
    cudaGetSymbolAddress((void**)&pcatW, g_catW);

    // init state + derived tensors
    prep_kernel<<<2080, 1024>>>(xs, argsort, dec_Wi, dec_Wh);

    // ---------------- encoder: 128 steps ----------------
    for (int t = 0; t < cL; t++) {
        gemm_abt<<<dim3(cH4 / 64, cB / 64), 256>>>(ph, enc_Wh, enc_b, pz, cB, cH4, cH);
        lstm_gates<<<(cB * cH) / 256, 256>>>(xs, enc_Wi, t, 1);
    }

    // enc_w1 = enc_out @ w1^T  (M = B*L = 32768)
    gemm_abt<<<dim3(cH / 64, (cB * cL) / 64), 256>>>(peo, w1, nullptr, pew1,
                                                     cB * cL, cH, cH);

    // ---------------- decoder: 128 steps ----------------
    for (int t = 0; t < cL; t++) {
        // q = h @ w2^T
        gemm_abt<<<dim3(cH / 64, cB / 64), 256>>>(ph, w2, nullptr, pq, cB, cH, cH);
        // scores + softmax + log_softmax(out) + context + x_cat
        attn_fused<<<cB, 512>>>(vt, t, out);
        // z = x_cat @ catW^T + dec_b   (k = 1040 padded)
        gemm_abt<<<dim3(cH4 / 64, cB / 64), 256>>>(pxcat, pcatW, dec_b, pz,
                                                   cB, cH4, KCAT);
        // h, c update
        lstm_gates<<<(cB * cH) / 256, 256>>>(xs, enc_Wi, t, 0);
    }
}

// round 7
// speedup vs baseline: 1.1098x; 1.1098x over previous
#include <cuda_runtime.h>
#include <math.h>
#include <cstdint>

// Problem constants
constexpr int cB  = 256;
constexpr int cL  = 128;
constexpr int cH  = 512;
constexpr int cH4 = 2048;
constexpr int KCAT = 1056;   // 512 ctx + 512 h + 1 scalar + pad to multiple of 32

// Persistent device scratch
__device__ float g_h[2][cB * cH];                   // ping-pong hidden state
__device__ float g_c[cB * cH];
__device__ float g_q[cB * cH];
__device__ float g_enc_out[(size_t)cB * cL * cH];   // 67 MB
__device__ float g_enc_w1[(size_t)cB * cL * cH];    // 67 MB
__device__ float g_xcat[cB * KCAT];
__device__ float g_Whx[(size_t)cH4 * cH];           // gate-interleaved enc_Wh
__device__ float g_catW[(size_t)cH4 * KCAT];        // gate-interleaved dec cat weights
__device__ float g_Wie[cH4];                        // gate-interleaved enc_Wi (column vec)
__device__ float g_be[cH4];                         // gate-interleaved enc bias
__device__ float g_bd[cH4];                         // gate-interleaved dec bias
__device__ float g_decin[cL * cB];

// ---------------- math helpers ----------------
__device__ __forceinline__ float acc_tanh(float x) {   // accurate (2 MUFU)
    float a = fabsf(x);
    float e = __expf(-2.0f * a);
    float r = __fdividef(1.0f - e, 1.0f + e);
    return copysignf(r, x);
}
__device__ __forceinline__ float acc_sig(float x) {
    return __fdividef(1.0f, 1.0f + __expf(-x));
}
__device__ __forceinline__ float mufu_tanh(float x) {  // 1 MUFU, abs err ~5e-4
    float y; asm("tanh.approx.f32 %0, %1;" : "=f"(y) : "f"(x)); return y;
}
__device__ __forceinline__ uint32_t f2tf32(float x) {
    uint32_t r; asm("cvt.rna.tf32.f32 %0, %1;" : "=r"(r) : "f"(x)); return r;
}
__device__ __forceinline__ void mma_tf32(float* d, const uint32_t* a, const uint32_t* b) {
    asm volatile("mma.sync.aligned.m16n8k8.row.col.f32.tf32.tf32.f32 "
                 "{%0,%1,%2,%3}, {%4,%5,%6,%7}, {%8,%9}, {%0,%1,%2,%3};"
                 : "+f"(d[0]), "+f"(d[1]), "+f"(d[2]), "+f"(d[3])
                 : "r"(a[0]), "r"(a[1]), "r"(a[2]), "r"(a[3]), "r"(b[0]), "r"(b[1]));
}

// ---------------- prep: permuted weights, teacher inputs, zero state ----------------
__global__ void prep_kernel(const int* __restrict__ xs, const int* __restrict__ as,
                            const float* __restrict__ encWi, const float* __restrict__ encWh,
                            const float* __restrict__ encB,
                            const float* __restrict__ decWi, const float* __restrict__ decWh,
                            const float* __restrict__ decB) {
    int stride = gridDim.x * blockDim.x;
    const int TOT = cH4 * KCAT;   // largest array
    for (int idx = blockIdx.x * blockDim.x + threadIdx.x; idx < TOT; idx += stride) {
        // catW: new row nr = 4j+g, source row r = g*512+j
        {
            int nr = idx / KCAT, k = idx - nr * KCAT;
            int j = nr >> 2, g = nr & 3;
            int r = g * cH + j;
            float v;
            if (k < cH)            v = decWi[r * (cH + 1) + k];
            else if (k < 2 * cH)   v = decWh[r * cH + (k - cH)];
            else if (k == 2 * cH)  v = decWi[r * (cH + 1) + cH];
            else                   v = 0.0f;
            g_catW[idx] = v;
        }
        if (idx < cH4 * cH) {
            int nr = idx / cH, k = idx - nr * cH;
            int j = nr >> 2, g = nr & 3;
            g_Whx[idx] = encWh[(g * cH + j) * cH + k];
        }
        if (idx < cH4) {
            int j = idx >> 2, g = idx & 3;
            g_Wie[idx] = encWi[g * cH + j];
            g_be[idx]  = encB[g * cH + j];
            g_bd[idx]  = decB[g * cH + j];
        }
        if (idx < cB * cH) { g_h[0][idx] = 0.0f; g_c[idx] = 0.0f; }
        if (idx < cB * KCAT) g_xcat[idx] = 0.0f;
        if (idx < cL * cB) {
            int tt = idx / cB, bb = idx - tt * cB;
            g_decin[idx] = (tt == 0) ? 0.0f
                         : (float)xs[bb * cL + as[bb * cL + tt - 1]];
        }
    }
}

// ---------------- tf32 mma.sync GEMM: C[M,N] = A[M,K] @ W[N,K]^T ----------------
// mode 0: plain store to C.
// mode 1: encoder LSTM gate epilogue (gate-interleaved N): z + be + xt*Wie -> h,c,enc_out
// mode 2: decoder LSTM gate epilogue: z + bd -> h,c
constexpr int BM = 64, BN = 64, BK = 32;
constexpr int TS = 40;   // smem row stride (8 mod 32 -> mild conflicts only)

__global__ __launch_bounds__(128)
void gemm_mma(const float* __restrict__ A, const float* __restrict__ W,
              float* __restrict__ C, const float* __restrict__ bias4,
              const int* __restrict__ xs, float* __restrict__ h_out,
              int M, int N, int K, int mode, int t) {
    __shared__ float sh[2 * BM * TS];          // 5120 floats; sZ (64x65=4160) reuses it
    float* sA = sh;
    float* sW = sh + BM * TS;

    int tid = threadIdx.x;
    int w = tid >> 5, lane = tid & 31;
    int grp = lane >> 2, qd = lane & 3;
    int n0 = blockIdx.x * BN, m0 = blockIdx.y * BM;

    float acc[8][4];
#pragma unroll
    for (int i = 0; i < 8; i++)
#pragma unroll
        for (int j = 0; j < 4; j++) acc[i][j] = 0.0f;

    for (int k0 = 0; k0 < K; k0 += BK) {
        // G2S: A tile 64x32, W tile 64x32 (convert to tf32)
#pragma unroll
        for (int i = 0; i < 4; i++) {
            int idx = tid + i * 128;
            int r = idx >> 3, c = (idx & 7) * 4;
            float4 v = *(const float4*)(A + (size_t)(m0 + r) * K + k0 + c);
            float4 s;
            s.x = __uint_as_float(f2tf32(v.x)); s.y = __uint_as_float(f2tf32(v.y));
            s.z = __uint_as_float(f2tf32(v.z)); s.w = __uint_as_float(f2tf32(v.w));
            *(float4*)(sA + r * TS + c) = s;
        }
#pragma unroll
        for (int i = 0; i < 4; i++) {
            int idx = tid + i * 128;
            int r = idx >> 3, c = (idx & 7) * 4;
            float4 v = *(const float4*)(W + (size_t)(n0 + r) * K + k0 + c);
            float4 s;
            s.x = __uint_as_float(f2tf32(v.x)); s.y = __uint_as_float(f2tf32(v.y));
            s.z = __uint_as_float(f2tf32(v.z)); s.w = __uint_as_float(f2tf32(v.w));
            *(float4*)(sW + r * TS + c) = s;
        }
        __syncthreads();

#pragma unroll
        for (int ks = 0; ks < BK; ks += 8) {
            uint32_t a[4];
            const float* ar = sA + (16 * w + grp) * TS + ks + qd;
            a[0] = __float_as_uint(ar[0]);
            a[1] = __float_as_uint(ar[8 * TS]);
            a[2] = __float_as_uint(ar[4]);
            a[3] = __float_as_uint(ar[8 * TS + 4]);
#pragma unroll
            for (int nt = 0; nt < 8; nt++) {
                uint32_t b[2];
                const float* br = sW + (8 * nt + grp) * TS + ks + qd;
                b[0] = __float_as_uint(br[0]);
                b[1] = __float_as_uint(br[4]);
                mma_tf32(acc[nt], a, b);
            }
        }
        __syncthreads();
    }

    if (mode == 0) {
        int mrow = m0 + 16 * w + grp;
#pragma unroll
        for (int nt = 0; nt < 8; nt++) {
            int col = n0 + 8 * nt + 2 * qd;
            C[(size_t)mrow * N + col]           = acc[nt][0];
            C[(size_t)mrow * N + col + 1]       = acc[nt][1];
            C[(size_t)(mrow + 8) * N + col]     = acc[nt][2];
            C[(size_t)(mrow + 8) * N + col + 1] = acc[nt][3];
        }
        return;
    }

    // ---- gate epilogue: stage z tile in smem, then per-unit LSTM update ----
    float* sZ = sh;                            // 64 rows x 65 stride
    int zr = 16 * w + grp;
#pragma unroll
    for (int nt = 0; nt < 8; nt++) {
        int col = 8 * nt + 2 * qd;
        sZ[zr * 65 + col]           = acc[nt][0];
        sZ[zr * 65 + col + 1]       = acc[nt][1];
        sZ[(zr + 8) * 65 + col]     = acc[nt][2];
        sZ[(zr + 8) * 65 + col + 1] = acc[nt][3];
    }
    __syncthreads();

#pragma unroll
    for (int i = 0; i < 8; i++) {
        int it = tid + i * 128;                // 1024 items: 64 rows x 16 units
        int row = it >> 4, u = it & 15;
        int b = m0 + row;
        int U = (n0 >> 2) + u;
        const float* zq = sZ + row * 65 + 4 * u;
        float zi = zq[0] + bias4[4 * U + 0];
        float zf = zq[1] + bias4[4 * U + 1];
        float zg = zq[2] + bias4[4 * U + 2];
        float zo = zq[3] + bias4[4 * U + 3];
        if (mode == 1) {
            float xt = (float)xs[b * cL + t];
            zi = fmaf(xt, g_Wie[4 * U + 0], zi);
            zf = fmaf(xt, g_Wie[4 * U + 1], zf);
            zg = fmaf(xt, g_Wie[4 * U + 2], zg);
            zo = fmaf(xt, g_Wie[4 * U + 3], zo);
        }
        float cold = g_c[b * cH + U];
        float cn = acc_sig(zf) * cold + acc_sig(zi) * acc_tanh(zg);
        float hn = acc_sig(zo) * acc_tanh(cn);
        g_c[b * cH + U] = cn;
        h_out[b * cH + U] = hn;
        if (mode == 1)
            g_enc_out[(size_t)(b * cL + t) * cH + U] = hn;
    }
}

// ---------------- fused attention ----------------
__global__ __launch_bounds__(512)
void attn_fused(const float* __restrict__ vt_p, int t, float* __restrict__ out,
                const float* __restrict__ hb) {
    __shared__ float qs[cH];
    __shared__ float vts[cH];
    __shared__ float sc[cL];
    __shared__ float ajs[cL];
    __shared__ float redm[16];
    __shared__ float reds[16];

    int b = blockIdx.x;
    int tid = threadIdx.x;
    int warp = tid >> 5, lane = tid & 31;

    for (int i = tid; i < cH; i += 512) {
        qs[i]  = g_q[b * cH + i];
        vts[i] = vt_p[i];
    }
    __syncthreads();

    // scores[l] = sum_j vt[j] * tanh(enc_w1[b,l,j] + q[b,j])
    for (int l = warp; l < cL; l += 16) {
        const float* row = g_enc_w1 + (size_t)(b * cL + l) * cH;
        float s = 0.0f;
#pragma unroll 4
        for (int j = lane; j < cH; j += 32)
            s = fmaf(vts[j], mufu_tanh(row[j] + qs[j]), s);
#pragma unroll
        for (int o = 16; o > 0; o >>= 1) s += __shfl_xor_sync(0xffffffffu, s, o);
        if (lane == 0) sc[l] = s;
    }
    __syncthreads();

    float sval = (tid < cL) ? sc[tid] : -3.0e38f;
    float m = sval;
#pragma unroll
    for (int o = 16; o > 0; o >>= 1) m = fmaxf(m, __shfl_xor_sync(0xffffffffu, m, o));
    if (lane == 0) redm[warp] = m;
    __syncthreads();
    if (tid < 16) {
        float mm = redm[tid];
#pragma unroll
        for (int o = 8; o > 0; o >>= 1) mm = fmaxf(mm, __shfl_xor_sync(0x0000ffffu, mm, o));
        if (tid == 0) redm[0] = mm;
    }
    __syncthreads();
    float mx = redm[0];

    float e = (tid < cL) ? __expf(sval - mx) : 0.0f;
    float ss = e;
#pragma unroll
    for (int o = 16; o > 0; o >>= 1) ss += __shfl_xor_sync(0xffffffffu, ss, o);
    if (lane == 0) reds[warp] = ss;
    __syncthreads();
    if (tid < 16) {
        float s2 = reds[tid];
#pragma unroll
        for (int o = 8; o > 0; o >>= 1) s2 += __shfl_xor_sync(0x0000ffffu, s2, o);
        if (tid == 0) reds[0] = s2;
    }
    __syncthreads();
    float tot = reds[0];

    if (tid < cL) {
        out[((size_t)b * cL + t) * cL + tid] = sval - mx - __logf(tot);
        ajs[tid] = __fdividef(e, tot);
    }
    __syncthreads();

    // context + x_cat assembly
    float acc = 0.0f;
    const float* eo = g_enc_out + (size_t)b * cL * cH + tid;
#pragma unroll 4
    for (int l = 0; l < cL; l++) acc = fmaf(ajs[l], eo[(size_t)l * cH], acc);

    g_xcat[b * KCAT + tid]      = acc;
    g_xcat[b * KCAT + cH + tid] = hb[b * cH + tid];
    if (tid == 0) g_xcat[b * KCAT + 2 * cH] = g_decin[t * cB + b];
}

// ---------------- host orchestration ----------------
extern "C" void kernel_launch(void* const* d_in, const int* in_sizes, int n_in,
                              void* d_out, int out_size) {
    const int*   xs      = (const int*)d_in[0];
    const int*   argsort = (const int*)d_in[2];
    const float* enc_Wi  = (const float*)d_in[3];
    const float* enc_Wh  = (const float*)d_in[4];
    const float* enc_b   = (const float*)d_in[5];
    const float* dec_Wi  = (const float*)d_in[6];
    const float* dec_Wh  = (const float*)d_in[7];
    const float* dec_b   = (const float*)d_in[8];
    const float* w1      = (const float*)d_in[9];
    const float* w2      = (const float*)d_in[10];
    const float* vt      = (const float*)d_in[11];
    float*       out     = (float*)d_out;

    float *ph0, *ph1, *pq, *peo, *pew1, *pxcat, *pWhx, *pcatW, *pbe, *pbd;
    cudaGetSymbolAddress((void**)&ph0,   g_h);          // g_h[0]
    ph1 = ph0 + cB * cH;                                // g_h[1]
    cudaGetSymbolAddress((void**)&pq,    g_q);
    cudaGetSymbolAddress((void**)&peo,   g_enc_out);
    cudaGetSymbolAddress((void**)&pew1,  g_enc_w1);
    cudaGetSymbolAddress((void**)&pxcat, g_xcat);
    cudaGetSymbolAddress((void**)&pWhx,  g_Whx);
    cudaGetSymbolAddress((void**)&pcatW, g_catW);
    cudaGetSymbolAddress((void**)&pbe,   g_be);
    cudaGetSymbolAddress((void**)&pbd,   g_bd);

    prep_kernel<<<2080, 1024>>>(xs, argsort, enc_Wi, enc_Wh, enc_b,
                                dec_Wi, dec_Wh, dec_b);

    float* hb[2] = {ph0, ph1};
    int cur = 0;

    // ---------------- encoder: 128 steps (1 kernel each) ----------------
    for (int t = 0; t < cL; t++) {
        gemm_mma<<<dim3(cH4 / BN, cB / BM), 128>>>(
            hb[cur], pWhx, nullptr, pbe, xs, hb[cur ^ 1],
            cB, cH4, cH, 1, t);
        cur ^= 1;
    }

    // enc_w1 = enc_out @ w1^T   (M = 32768)
    gemm_mma<<<dim3(cH / BN, (cB * cL) / BM), 128>>>(
        peo, w1, pew1, nullptr, nullptr, nullptr,
        cB * cL, cH, cH, 0, 0);

    // ---------------- decoder: 128 steps (3 kernels each) ----------------
    for (int t = 0; t < cL; t++) {
        gemm_mma<<<dim3(cH / BN, cB / BM), 128>>>(
            hb[cur], w2, pq, nullptr, nullptr, nullptr,
            cB, cH, cH, 0, 0);
        attn_fused<<<cB, 512>>>(vt, t, out, hb[cur]);
        gemm_mma<<<dim3(cH4 / BN, cB / BM), 128>>>(
            pxcat, pcatW, nullptr, pbd, nullptr, hb[cur ^ 1],
            cB, cH4, KCAT, 2, t);
        cur ^= 1;
    }
}

// round 10
// speedup vs baseline: 2.0150x; 1.8156x over previous
#include <cuda_runtime.h>
#include <math.h>
#include <cstdint>

// Problem constants
constexpr int cB  = 256;
constexpr int cL  = 128;
constexpr int cH  = 512;
constexpr int cH4 = 2048;
constexpr int KCAT = 1056;   // 512 ctx + 512 h + 1 scalar + pad to multiple of 32

// Persistent device scratch
__device__ float g_h[2][cB * cH];                   // ping-pong hidden state (tf32-rounded)
__device__ float g_c[cB * cH];
__device__ float g_q[cB * cH];
__device__ float g_enc_out[(size_t)cB * cL * cH];   // tf32-rounded
__device__ float g_enc_w1[(size_t)cB * cL * cH];
__device__ float g_xcat[cB * KCAT];                 // tf32-rounded
__device__ float g_Whx[(size_t)cH4 * cH];           // gate-interleaved enc_Wh (tf32)
__device__ float g_catW[(size_t)cH4 * KCAT];        // gate-interleaved dec cat W (tf32)
__device__ float g_w1c[(size_t)cH * cH];            // w1 (tf32)
__device__ float g_w2c[(size_t)cH * cH];            // w2 (tf32)
__device__ float g_Wie[cH4];
__device__ float g_be[cH4];
__device__ float g_bd[cH4];
__device__ float g_decin[cL * cB];

// ---------------- math helpers ----------------
__device__ __forceinline__ float acc_tanh(float x) {
    float a = fabsf(x);
    float e = __expf(-2.0f * a);
    float r = __fdividef(1.0f - e, 1.0f + e);
    return copysignf(r, x);
}
__device__ __forceinline__ float acc_sig(float x) {
    return __fdividef(1.0f, 1.0f + __expf(-x));
}
__device__ __forceinline__ float mufu_tanh(float x) {
    float y; asm("tanh.approx.f32 %0, %1;" : "=f"(y) : "f"(x)); return y;
}
__device__ __forceinline__ uint32_t f2tf32(float x) {
    uint32_t r; asm("cvt.rna.tf32.f32 %0, %1;" : "=r"(r) : "f"(x)); return r;
}
__device__ __forceinline__ float rndtf(float x) { return __uint_as_float(f2tf32(x)); }

__device__ __forceinline__ void mma_tf32(float* d, const uint32_t* a, const uint32_t* b) {
    asm volatile("mma.sync.aligned.m16n8k8.row.col.f32.tf32.tf32.f32 "
                 "{%0,%1,%2,%3}, {%4,%5,%6,%7}, {%8,%9}, {%0,%1,%2,%3};"
                 : "+f"(d[0]), "+f"(d[1]), "+f"(d[2]), "+f"(d[3])
                 : "r"(a[0]), "r"(a[1]), "r"(a[2]), "r"(a[3]), "r"(b[0]), "r"(b[1]));
}

__device__ __forceinline__ uint32_t smem_u32(const void* p) {
    uint32_t a;
    asm("{ .reg .u64 t; cvta.to.shared.u64 t, %1; cvt.u32.u64 %0, t; }" : "=r"(a) : "l"(p));
    return a;
}
#define CP_ASYNC16(dst, src) \
    asm volatile("cp.async.ca.shared.global [%0], [%1], 16;" :: "r"(dst), "l"(src) : "memory")
#define CP_COMMIT() asm volatile("cp.async.commit_group;" ::: "memory")
#define CP_WAIT(n)  asm volatile("cp.async.wait_group %0;" :: "n"(n) : "memory")

// ---------------- prep: permuted + tf32-rounded weights, teacher inputs ----------------
__global__ void prep_kernel(const int* __restrict__ xs, const int* __restrict__ as,
                            const float* __restrict__ encWi, const float* __restrict__ encWh,
                            const float* __restrict__ encB,
                            const float* __restrict__ decWi, const float* __restrict__ decWh,
                            const float* __restrict__ decB,
                            const float* __restrict__ w1, const float* __restrict__ w2) {
    int stride = gridDim.x * blockDim.x;
    const int TOT = cH4 * KCAT;
    for (int idx = blockIdx.x * blockDim.x + threadIdx.x; idx < TOT; idx += stride) {
        {   // catW: new row 4j+g <- source row g*512+j; tf32-rounded
            int nr = idx / KCAT, k = idx - nr * KCAT;
            int j = nr >> 2, g = nr & 3;
            int r = g * cH + j;
            float v;
            if (k < cH)            v = decWi[r * (cH + 1) + k];
            else if (k < 2 * cH)   v = decWh[r * cH + (k - cH)];
            else if (k == 2 * cH)  v = decWi[r * (cH + 1) + cH];
            else                   v = 0.0f;
            g_catW[idx] = rndtf(v);
        }
        if (idx < cH4 * cH) {
            int nr = idx / cH, k = idx - nr * cH;
            int j = nr >> 2, g = nr & 3;
            g_Whx[idx] = rndtf(encWh[(g * cH + j) * cH + k]);
        }
        if (idx < cH * cH) {
            g_w1c[idx] = rndtf(w1[idx]);
            g_w2c[idx] = rndtf(w2[idx]);
        }
        if (idx < cH4) {
            int j = idx >> 2, g = idx & 3;
            g_Wie[idx] = encWi[g * cH + j];
            g_be[idx]  = encB[g * cH + j];
            g_bd[idx]  = decB[g * cH + j];
        }
        if (idx < cB * cH) { g_h[0][idx] = 0.0f; g_c[idx] = 0.0f; }
        if (idx < cB * KCAT) g_xcat[idx] = 0.0f;
        if (idx < cL * cB) {
            int tt = idx / cB, bb = idx - tt * cB;
            g_decin[idx] = (tt == 0) ? 0.0f
                         : rndtf((float)xs[bb * cL + as[bb * cL + tt - 1]]);
        }
    }
}

// ---------------- pipelined tf32 mma.sync GEMM: C[M,N] = A[M,K] @ W[N,K]^T ----------------
// Operands must already be tf32-rounded (weights in prep; activations at production site).
// mode 0: plain store. mode 1: enc LSTM gates. mode 2: dec LSTM gates.
constexpr int BM = 64, BN = 64, BK = 32;
constexpr int TS = 36;       // smem row stride (floats); 16B-aligned rows, conflict-free frags
constexpr int STAGES = 3;
constexpr int STF = BM * TS; // floats per stage per operand (2304)

__global__ __launch_bounds__(128)
void gemm_mma(const float* __restrict__ A, const float* __restrict__ W,
              float* __restrict__ C, const float* __restrict__ bias4,
              const int* __restrict__ xs, float* __restrict__ h_out,
              int M, int N, int K, int mode, int t) {
    __shared__ float sA[STAGES * STF];
    __shared__ float sW[STAGES * STF];

    int tid = threadIdx.x;
    int w = tid >> 5, lane = tid & 31;
    int grp = lane >> 2, qd = lane & 3;
    int n0 = blockIdx.x * BN, m0 = blockIdx.y * BM;

    uint32_t sA_u = smem_u32(sA);
    uint32_t sW_u = smem_u32(sW);
    const float* Ab = A + (size_t)m0 * K;
    const float* Wb = W + (size_t)n0 * K;

    // per-thread fixed load slots: 4 rows apart, 8 threads per row (4 floats each)
    int lr = tid >> 3;            // 0..15 (row group base; +16 per it)
    int lc = (tid & 7) * 4;       // col within 32

    float acc[8][4];
#pragma unroll
    for (int i = 0; i < 8; i++)
#pragma unroll
        for (int j = 0; j < 4; j++) acc[i][j] = 0.0f;

    const int NC = K / BK;

    // prologue: issue chunks 0..STAGES-2
#pragma unroll
    for (int pc = 0; pc < STAGES - 1; pc++) {
        int koff = pc * BK;
#pragma unroll
        for (int it = 0; it < 4; it++) {
            int r = lr + it * 16;
            CP_ASYNC16(sA_u + (uint32_t)(pc * STF + r * TS + lc) * 4,
                       Ab + (size_t)r * K + koff + lc);
            CP_ASYNC16(sW_u + (uint32_t)(pc * STF + r * TS + lc) * 4,
                       Wb + (size_t)r * K + koff + lc);
        }
        CP_COMMIT();
    }

    for (int i = 0; i < NC; i++) {
        int nxt = i + STAGES - 1;
        if (nxt < NC) {
            int st = nxt % STAGES;
            int koff = nxt * BK;
#pragma unroll
            for (int it = 0; it < 4; it++) {
                int r = lr + it * 16;
                CP_ASYNC16(sA_u + (uint32_t)(st * STF + r * TS + lc) * 4,
                           Ab + (size_t)r * K + koff + lc);
                CP_ASYNC16(sW_u + (uint32_t)(st * STF + r * TS + lc) * 4,
                           Wb + (size_t)r * K + koff + lc);
            }
            CP_COMMIT();
            CP_WAIT(STAGES - 2);
        } else {
            CP_WAIT(0);
        }
        __syncthreads();

        const float* aS = sA + (i % STAGES) * STF;
        const float* wS = sW + (i % STAGES) * STF;
#pragma unroll
        for (int ks = 0; ks < BK; ks += 8) {
            uint32_t a[4];
            const float* ar = aS + (16 * w + grp) * TS + ks + qd;
            a[0] = __float_as_uint(ar[0]);
            a[1] = __float_as_uint(ar[8 * TS]);
            a[2] = __float_as_uint(ar[4]);
            a[3] = __float_as_uint(ar[8 * TS + 4]);
#pragma unroll
            for (int nt = 0; nt < 8; nt++) {
                uint32_t b[2];
                const float* br = wS + (8 * nt + grp) * TS + ks + qd;
                b[0] = __float_as_uint(br[0]);
                b[1] = __float_as_uint(br[4]);
                mma_tf32(acc[nt], a, b);
            }
        }
        __syncthreads();
    }

    if (mode == 0) {
        int mrow = m0 + 16 * w + grp;
#pragma unroll
        for (int nt = 0; nt < 8; nt++) {
            int col = n0 + 8 * nt + 2 * qd;
            C[(size_t)mrow * N + col]           = acc[nt][0];
            C[(size_t)mrow * N + col + 1]       = acc[nt][1];
            C[(size_t)(mrow + 8) * N + col]     = acc[nt][2];
            C[(size_t)(mrow + 8) * N + col + 1] = acc[nt][3];
        }
        return;
    }

    // ---- gate epilogue: stage z tile in smem (reuse sA: 64x65 = 4160 <= 3*2304) ----
    float* sZ = sA;
    int zr = 16 * w + grp;
#pragma unroll
    for (int nt = 0; nt < 8; nt++) {
        int col = 8 * nt + 2 * qd;
        sZ[zr * 65 + col]           = acc[nt][0];
        sZ[zr * 65 + col + 1]       = acc[nt][1];
        sZ[(zr + 8) * 65 + col]     = acc[nt][2];
        sZ[(zr + 8) * 65 + col + 1] = acc[nt][3];
    }
    __syncthreads();

#pragma unroll
    for (int i = 0; i < 8; i++) {
        int it = tid + i * 128;               // 1024 items: 64 rows x 16 units
        int row = it >> 4, u = it & 15;
        int b = m0 + row;
        int U = (n0 >> 2) + u;
        const float* zq = sZ + row * 65 + 4 * u;
        float zi = zq[0] + bias4[4 * U + 0];
        float zf = zq[1] + bias4[4 * U + 1];
        float zg = zq[2] + bias4[4 * U + 2];
        float zo = zq[3] + bias4[4 * U + 3];
        if (mode == 1) {
            float xt = (float)xs[b * cL + t];
            zi = fmaf(xt, g_Wie[4 * U + 0], zi);
            zf = fmaf(xt, g_Wie[4 * U + 1], zf);
            zg = fmaf(xt, g_Wie[4 * U + 2], zg);
            zo = fmaf(xt, g_Wie[4 * U + 3], zo);
        }
        float cold = g_c[b * cH + U];
        float cn = acc_sig(zf) * cold + acc_sig(zi) * acc_tanh(zg);
        float hn = acc_sig(zo) * acc_tanh(cn);
        g_c[b * cH + U] = cn;
        float hr = rndtf(hn);                 // tf32-rounded: next GEMM A-operand
        h_out[b * cH + U] = hr;
        if (mode == 1)
            g_enc_out[(size_t)(b * cL + t) * cH + U] = hr;
    }
}

// ---------------- fused attention ----------------
__global__ __launch_bounds__(512)
void attn_fused(const float* __restrict__ vt_p, int t, float* __restrict__ out,
                const float* __restrict__ hb) {
    __shared__ float qs[cH];
    __shared__ float vts[cH];
    __shared__ float sc[cL];
    __shared__ float ajs[cL];
    __shared__ float redm[16];
    __shared__ float reds[16];

    int b = blockIdx.x;
    int tid = threadIdx.x;
    int warp = tid >> 5, lane = tid & 31;

    for (int i = tid; i < cH; i += 512) {
        qs[i]  = g_q[b * cH + i];
        vts[i] = vt_p[i];
    }
    __syncthreads();

    for (int l = warp; l < cL; l += 16) {
        const float* row = g_enc_w1 + (size_t)(b * cL + l) * cH;
        float s = 0.0f;
#pragma unroll 4
        for (int j = lane; j < cH; j += 32)
            s = fmaf(vts[j], mufu_tanh(row[j] + qs[j]), s);
#pragma unroll
        for (int o = 16; o > 0; o >>= 1) s += __shfl_xor_sync(0xffffffffu, s, o);
        if (lane == 0) sc[l] = s;
    }
    __syncthreads();

    float sval = (tid < cL) ? sc[tid] : -3.0e38f;
    float m = sval;
#pragma unroll
    for (int o = 16; o > 0; o >>= 1) m = fmaxf(m, __shfl_xor_sync(0xffffffffu, m, o));
    if (lane == 0) redm[warp] = m;
    __syncthreads();
    if (tid < 16) {
        float mm = redm[tid];
#pragma unroll
        for (int o = 8; o > 0; o >>= 1) mm = fmaxf(mm, __shfl_xor_sync(0x0000ffffu, mm, o));
        if (tid == 0) redm[0] = mm;
    }
    __syncthreads();
    float mx = redm[0];

    float e = (tid < cL) ? __expf(sval - mx) : 0.0f;
    float ss = e;
#pragma unroll
    for (int o = 16; o > 0; o >>= 1) ss += __shfl_xor_sync(0xffffffffu, ss, o);
    if (lane == 0) reds[warp] = ss;
    __syncthreads();
    if (tid < 16) {
        float s2 = reds[tid];
#pragma unroll
        for (int o = 8; o > 0; o >>= 1) s2 += __shfl_xor_sync(0x0000ffffu, s2, o);
        if (tid == 0) reds[0] = s2;
    }
    __syncthreads();
    float tot = reds[0];

    if (tid < cL) {
        out[((size_t)b * cL + t) * cL + tid] = sval - mx - __logf(tot);
        ajs[tid] = __fdividef(e, tot);
    }
    __syncthreads();

    float acc = 0.0f;
    const float* eo = g_enc_out + (size_t)b * cL * cH + tid;
#pragma unroll 8
    for (int l = 0; l < cL; l++) acc = fmaf(ajs[l], eo[(size_t)l * cH], acc);

    // tf32-rounded: next GEMM A-operand
    g_xcat[b * KCAT + tid]      = rndtf(acc);
    g_xcat[b * KCAT + cH + tid] = hb[b * cH + tid];   // already rounded at production
    if (tid == 0) g_xcat[b * KCAT + 2 * cH] = g_decin[t * cB + b];
}

// ---------------- host orchestration ----------------
extern "C" void kernel_launch(void* const* d_in, const int* in_sizes, int n_in,
                              void* d_out, int out_size) {
    const int*   xs      = (const int*)d_in[0];
    const int*   argsort = (const int*)d_in[2];
    const float* enc_Wi  = (const float*)d_in[3];
    const float* enc_Wh  = (const float*)d_in[4];
    const float* enc_b   = (const float*)d_in[5];
    const float* dec_Wi  = (const float*)d_in[6];
    const float* dec_Wh  = (const float*)d_in[7];
    const float* dec_b   = (const float*)d_in[8];
    const float* w1      = (const float*)d_in[9];
    const float* w2      = (const float*)d_in[10];
    const float* vt      = (const float*)d_in[11];
    float*       out     = (float*)d_out;

    float *ph0, *ph1, *pq, *peo, *pew1, *pxcat, *pWhx, *pcatW, *pbe, *pbd, *pw1c, *pw2c;
    cudaGetSymbolAddress((void**)&ph0,   g_h);
    ph1 = ph0 + cB * cH;
    cudaGetSymbolAddress((void**)&pq,    g_q);
    cudaGetSymbolAddress((void**)&peo,   g_enc_out);
    cudaGetSymbolAddress((void**)&pew1,  g_enc_w1);
    cudaGetSymbolAddress((void**)&pxcat, g_xcat);
    cudaGetSymbolAddress((void**)&pWhx,  g_Whx);
    cudaGetSymbolAddress((void**)&pcatW, g_catW);
    cudaGetSymbolAddress((void**)&pbe,   g_be);
    cudaGetSymbolAddress((void**)&pbd,   g_bd);
    cudaGetSymbolAddress((void**)&pw1c,  g_w1c);
    cudaGetSymbolAddress((void**)&pw2c,  g_w2c);

    prep_kernel<<<2080, 1024>>>(xs, argsort, enc_Wi, enc_Wh, enc_b,
                                dec_Wi, dec_Wh, dec_b, w1, w2);

    float* hb[2] = {ph0, ph1};
    int cur = 0;

    // ---------------- encoder: 128 steps (1 kernel each) ----------------
    for (int t = 0; t < cL; t++) {
        gemm_mma<<<dim3(cH4 / BN, cB / BM), 128>>>(
            hb[cur], pWhx, nullptr, pbe, xs, hb[cur ^ 1],
            cB, cH4, cH, 1, t);
        cur ^= 1;
    }

    // enc_w1 = enc_out @ w1^T   (M = 32768)
    gemm_mma<<<dim3(cH / BN, (cB * cL) / BM), 128>>>(
        peo, pw1c, pew1, nullptr, nullptr, nullptr,
        cB * cL, cH, cH, 0, 0);

    // ---------------- decoder: 128 steps (3 kernels each) ----------------
    for (int t = 0; t < cL; t++) {
        gemm_mma<<<dim3(cH / BN, cB / BM), 128>>>(
            hb[cur], pw2c, pq, nullptr, nullptr, nullptr,
            cB, cH, cH, 0, 0);
        attn_fused<<<cB, 512>>>(vt, t, out, hb[cur]);
        gemm_mma<<<dim3(cH4 / BN, cB / BM), 128>>>(
            pxcat, pcatW, nullptr, pbd, nullptr, hb[cur ^ 1],
            cB, cH4, KCAT, 2, t);
        cur ^= 1;
    }
}

// round 11
// speedup vs baseline: 4.2691x; 2.1186x over previous
#include <cuda_runtime.h>
#include <cuda_bf16.h>
#include <math.h>
#include <cstdint>

// Problem constants
constexpr int cB  = 256;
constexpr int cL  = 128;
constexpr int cH  = 512;
constexpr int cH4 = 2048;
constexpr int KCAT = 1024;   // 512 ctx + 512 h (scalar handled fp32 in epilogue)

typedef __nv_bfloat16 bf16;

// Persistent device scratch (bf16 GEMM operands, fp32 state where it matters)
__device__ __align__(16) bf16  g_hb[2][cB * cH];          // ping-pong hidden (bf16)
__device__ float g_c[cB * cH];                            // cell state fp32
__device__ float g_q[cB * cH];                            // q = h@w2^T (fp32)
__device__ __align__(16) bf16  g_enc_outb[(size_t)cB * cL * cH];  // 33.5 MB
__device__ __align__(16) bf16  g_enc_w1b[(size_t)cB * cL * cH];   // 33.5 MB
__device__ __align__(16) bf16  g_xcatb[cB * KCAT];
__device__ __align__(16) bf16  g_Whx[(size_t)cH4 * cH];           // gate-interleaved enc_Wh
__device__ __align__(16) bf16  g_catW[(size_t)cH4 * KCAT];        // gate-interleaved dec W
__device__ __align__(16) bf16  g_w1b[(size_t)cH * cH];
__device__ __align__(16) bf16  g_w2b[(size_t)cH * cH];
__device__ float g_Wie[cH4];     // enc input weight (gate-interleaved)
__device__ float g_Wid[cH4];     // dec scalar-input weight (gate-interleaved)
__device__ float g_be[cH4];
__device__ float g_bd[cH4];
__device__ float g_decin[cL * cB];   // raw fp32 teacher-forced inputs

// ---------------- math helpers ----------------
__device__ __forceinline__ float acc_tanh(float x) {
    float a = fabsf(x);
    float e = __expf(-2.0f * a);
    float r = __fdividef(1.0f - e, 1.0f + e);
    return copysignf(r, x);
}
__device__ __forceinline__ float acc_sig(float x) {
    return __fdividef(1.0f, 1.0f + __expf(-x));
}
__device__ __forceinline__ float mufu_tanh(float x) {
    float y; asm("tanh.approx.f32 %0, %1;" : "=f"(y) : "f"(x)); return y;
}
__device__ __forceinline__ void mma_bf16(float* d, const uint32_t* a, const uint32_t* b) {
    asm volatile("mma.sync.aligned.m16n8k16.row.col.f32.bf16.bf16.f32 "
                 "{%0,%1,%2,%3}, {%4,%5,%6,%7}, {%8,%9}, {%0,%1,%2,%3};"
                 : "+f"(d[0]), "+f"(d[1]), "+f"(d[2]), "+f"(d[3])
                 : "r"(a[0]), "r"(a[1]), "r"(a[2]), "r"(a[3]), "r"(b[0]), "r"(b[1]));
}
__device__ __forceinline__ uint32_t smem_u32(const void* p) {
    uint32_t a;
    asm("{ .reg .u64 t; cvta.to.shared.u64 t, %1; cvt.u32.u64 %0, t; }" : "=r"(a) : "l"(p));
    return a;
}
#define CP_ASYNC16(dst, src) \
    asm volatile("cp.async.ca.shared.global [%0], [%1], 16;" :: "r"(dst), "l"(src) : "memory")
#define CP_COMMIT() asm volatile("cp.async.commit_group;" ::: "memory")
#define CP_WAIT(n)  asm volatile("cp.async.wait_group %0;" :: "n"(n) : "memory")

// ---------------- prep: permuted bf16 weights, teacher inputs, state ----------------
__global__ void prep_kernel(const int* __restrict__ xs, const int* __restrict__ as,
                            const float* __restrict__ encWi, const float* __restrict__ encWh,
                            const float* __restrict__ encB,
                            const float* __restrict__ decWi, const float* __restrict__ decWh,
                            const float* __restrict__ decB,
                            const float* __restrict__ w1, const float* __restrict__ w2) {
    int stride = gridDim.x * blockDim.x;
    const int TOT = cH4 * KCAT;
    for (int idx = blockIdx.x * blockDim.x + threadIdx.x; idx < TOT; idx += stride) {
        {   // catW: new row 4j+g <- source row g*512+j
            int nr = idx >> 10, k = idx & 1023;
            int j = nr >> 2, g = nr & 3;
            int r = g * cH + j;
            float v = (k < cH) ? decWi[r * (cH + 1) + k]
                               : decWh[r * cH + (k - cH)];
            g_catW[idx] = __float2bfloat16_rn(v);
        }
        if (idx < cH4 * cH) {
            int nr = idx >> 9, k = idx & 511;
            int j = nr >> 2, g = nr & 3;
            g_Whx[idx] = __float2bfloat16_rn(encWh[(g * cH + j) * cH + k]);
        }
        if (idx < cH * cH) {
            g_w1b[idx] = __float2bfloat16_rn(w1[idx]);
            g_w2b[idx] = __float2bfloat16_rn(w2[idx]);
        }
        if (idx < cH4) {
            int j = idx >> 2, g = idx & 3;
            g_Wie[idx] = encWi[g * cH + j];
            g_Wid[idx] = decWi[(g * cH + j) * (cH + 1) + cH];
            g_be[idx]  = encB[g * cH + j];
            g_bd[idx]  = decB[g * cH + j];
        }
        if (idx < cB * cH) { g_hb[0][idx] = __float2bfloat16_rn(0.0f); g_c[idx] = 0.0f; }
        if (idx < cL * cB) {
            int tt = idx / cB, bb = idx - tt * cB;
            g_decin[idx] = (tt == 0) ? 0.0f
                         : (float)xs[bb * cL + as[bb * cL + tt - 1]];
        }
    }
}

// ---------------- pipelined bf16 mma GEMM: C[M,N] = A[M,K] @ W[N,K]^T ----------------
// mode 0: fp32 store to C. mode 3: bf16 store to Cb.
// mode 1: enc LSTM gates (x from xs). mode 2: dec LSTM gates (x from g_decin).
constexpr int BM = 64, BN = 64, BK = 32;     // elements (bf16)
constexpr int TSB = 40;                      // smem row stride in bf16 (80 B, 16B-mult)
constexpr int STAGES = 4;
constexpr int STE = BM * TSB;                // bf16 per stage per operand

__global__ __launch_bounds__(128)
void gemm_mma(const bf16* __restrict__ A, const bf16* __restrict__ W,
              float* __restrict__ C, bf16* __restrict__ Cb,
              const float* __restrict__ bias4,
              const int* __restrict__ xs, bf16* __restrict__ h_out,
              int M, int N, int K, int mode, int t) {
    __shared__ __align__(16) bf16 sA[STAGES * STE];
    __shared__ __align__(16) bf16 sW[STAGES * STE];

    int tid = threadIdx.x;
    int w = tid >> 5, lane = tid & 31;
    int g4 = lane >> 2, q2 = (lane & 3) * 2;
    int n0 = blockIdx.x * BN, m0 = blockIdx.y * BM;

    uint32_t sA_u = smem_u32(sA);
    uint32_t sW_u = smem_u32(sW);
    const bf16* Ab = A + (size_t)m0 * K;
    const bf16* Wb = W + (size_t)n0 * K;

    // cp.async slots: 64 rows x 4 x 16B per tile; 128 threads -> 2 slots each
    int lr = tid >> 2;          // 0..31 (+32 second pass)
    int lc8 = (tid & 3) * 8;    // bf16 col offset (16B granules)

    float acc[8][4];
#pragma unroll
    for (int i = 0; i < 8; i++)
#pragma unroll
        for (int j = 0; j < 4; j++) acc[i][j] = 0.0f;

    const int NC = K / BK;

    // prologue: stages 0..STAGES-2
#pragma unroll
    for (int pc = 0; pc < STAGES - 1; pc++) {
        int koff = pc * BK;
#pragma unroll
        for (int it = 0; it < 2; it++) {
            int r = lr + it * 32;
            CP_ASYNC16(sA_u + (uint32_t)(pc * STE + r * TSB + lc8) * 2,
                       Ab + (size_t)r * K + koff + lc8);
            CP_ASYNC16(sW_u + (uint32_t)(pc * STE + r * TSB + lc8) * 2,
                       Wb + (size_t)r * K + koff + lc8);
        }
        CP_COMMIT();
    }

    for (int i = 0; i < NC; i++) {
        // wait until stage i resident
        int rem = NC - 1 - i;
        if (rem >= STAGES - 2) { CP_WAIT(STAGES - 2); }
        else if (rem == 2)     { CP_WAIT(2); }
        else if (rem == 1)     { CP_WAIT(1); }
        else                   { CP_WAIT(0); }
        __syncthreads();   // stage i ready AND all reads of stage (i-1) done

        int nxt = i + STAGES - 1;
        if (nxt < NC) {    // overwrite buffer of stage i-1 (safe after sync)
            int st = nxt % STAGES;
            int koff = nxt * BK;
#pragma unroll
            for (int it = 0; it < 2; it++) {
                int r = lr + it * 32;
                CP_ASYNC16(sA_u + (uint32_t)(st * STE + r * TSB + lc8) * 2,
                           Ab + (size_t)r * K + koff + lc8);
                CP_ASYNC16(sW_u + (uint32_t)(st * STE + r * TSB + lc8) * 2,
                           Wb + (size_t)r * K + koff + lc8);
            }
            CP_COMMIT();
        }

        const bf16* aS = sA + (i % STAGES) * STE;
        const bf16* wS = sW + (i % STAGES) * STE;
#pragma unroll
        for (int ks = 0; ks < BK; ks += 16) {
            uint32_t a[4];
            const bf16* ar = aS + (16 * w + g4) * TSB + ks + q2;
            a[0] = *(const uint32_t*)(ar);
            a[1] = *(const uint32_t*)(ar + 8 * TSB);
            a[2] = *(const uint32_t*)(ar + 8);
            a[3] = *(const uint32_t*)(ar + 8 * TSB + 8);
#pragma unroll
            for (int nt = 0; nt < 8; nt++) {
                uint32_t b[2];
                const bf16* br = wS + (8 * nt + g4) * TSB + ks + q2;
                b[0] = *(const uint32_t*)(br);
                b[1] = *(const uint32_t*)(br + 8);
                mma_bf16(acc[nt], a, b);
            }
        }
    }
    __syncthreads();

    if (mode == 0) {
        int mrow = m0 + 16 * w + g4;
#pragma unroll
        for (int nt = 0; nt < 8; nt++) {
            int col = n0 + 8 * nt + q2;
            C[(size_t)mrow * N + col]           = acc[nt][0];
            C[(size_t)mrow * N + col + 1]       = acc[nt][1];
            C[(size_t)(mrow + 8) * N + col]     = acc[nt][2];
            C[(size_t)(mrow + 8) * N + col + 1] = acc[nt][3];
        }
        return;
    }
    if (mode == 3) {
        int mrow = m0 + 16 * w + g4;
#pragma unroll
        for (int nt = 0; nt < 8; nt++) {
            int col = n0 + 8 * nt + q2;
            __nv_bfloat162 p0; p0.x = __float2bfloat16_rn(acc[nt][0]); p0.y = __float2bfloat16_rn(acc[nt][1]);
            __nv_bfloat162 p1; p1.x = __float2bfloat16_rn(acc[nt][2]); p1.y = __float2bfloat16_rn(acc[nt][3]);
            *(__nv_bfloat162*)&Cb[(size_t)mrow * N + col]       = p0;
            *(__nv_bfloat162*)&Cb[(size_t)(mrow + 8) * N + col] = p1;
        }
        return;
    }

    // ---- gate epilogue: stage z tile (fp32 64x65) in smem, reuse sA region ----
    float* sZ = (float*)sA;
    int zr = 16 * w + g4;
#pragma unroll
    for (int nt = 0; nt < 8; nt++) {
        int col = 8 * nt + q2;
        sZ[zr * 65 + col]           = acc[nt][0];
        sZ[zr * 65 + col + 1]       = acc[nt][1];
        sZ[(zr + 8) * 65 + col]     = acc[nt][2];
        sZ[(zr + 8) * 65 + col + 1] = acc[nt][3];
    }
    __syncthreads();

#pragma unroll
    for (int i = 0; i < 8; i++) {
        int it = tid + i * 128;               // 1024 items: 64 rows x 16 units
        int row = it >> 4, u = it & 15;
        int b = m0 + row;
        int U = (n0 >> 2) + u;
        const float* zq = sZ + row * 65 + 4 * u;
        float zi = zq[0] + bias4[4 * U + 0];
        float zf = zq[1] + bias4[4 * U + 1];
        float zg = zq[2] + bias4[4 * U + 2];
        float zo = zq[3] + bias4[4 * U + 3];
        float xt = (mode == 1) ? (float)xs[b * cL + t] : g_decin[t * cB + b];
        const float* Wv = (mode == 1) ? g_Wie : g_Wid;
        zi = fmaf(xt, Wv[4 * U + 0], zi);
        zf = fmaf(xt, Wv[4 * U + 1], zf);
        zg = fmaf(xt, Wv[4 * U + 2], zg);
        zo = fmaf(xt, Wv[4 * U + 3], zo);
        float cold = g_c[b * cH + U];
        float cn = acc_sig(zf) * cold + acc_sig(zi) * acc_tanh(zg);
        float hn = acc_sig(zo) * acc_tanh(cn);
        g_c[b * cH + U] = cn;
        bf16 hr = __float2bfloat16_rn(hn);
        h_out[b * cH + U] = hr;
        if (mode == 1)
            g_enc_outb[(size_t)(b * cL + t) * cH + U] = hr;
    }
}

// ---------------- fused attention (bf16 enc_w1/enc_out) ----------------
__global__ __launch_bounds__(512)
void attn_fused(const float* __restrict__ vt_p, int t, float* __restrict__ out,
                const bf16* __restrict__ hb) {
    __shared__ float qs[cH];
    __shared__ float vts[cH];
    __shared__ float sc[cL];
    __shared__ float ajs[cL];
    __shared__ float redm[16];
    __shared__ float reds[16];

    int b = blockIdx.x;
    int tid = threadIdx.x;
    int warp = tid >> 5, lane = tid & 31;

    for (int i = tid; i < cH; i += 512) {
        qs[i]  = g_q[b * cH + i];
        vts[i] = vt_p[i];
    }
    __syncthreads();

    // scores[l] = sum_j vt[j] * tanh(enc_w1[b,l,j] + q[b,j])
    for (int l = warp; l < cL; l += 16) {
        const __nv_bfloat162* row =
            (const __nv_bfloat162*)(g_enc_w1b + (size_t)(b * cL + l) * cH);
        float s = 0.0f;
#pragma unroll 4
        for (int j = lane; j < cH / 2; j += 32) {
            __nv_bfloat162 p = row[j];
            float2 qv = *(const float2*)(qs + 2 * j);
            float2 vv = *(const float2*)(vts + 2 * j);
            s = fmaf(vv.x, mufu_tanh(__bfloat162float(p.x) + qv.x), s);
            s = fmaf(vv.y, mufu_tanh(__bfloat162float(p.y) + qv.y), s);
        }
#pragma unroll
        for (int o = 16; o > 0; o >>= 1) s += __shfl_xor_sync(0xffffffffu, s, o);
        if (lane == 0) sc[l] = s;
    }
    __syncthreads();

    float sval = (tid < cL) ? sc[tid] : -3.0e38f;
    float m = sval;
#pragma unroll
    for (int o = 16; o > 0; o >>= 1) m = fmaxf(m, __shfl_xor_sync(0xffffffffu, m, o));
    if (lane == 0) redm[warp] = m;
    __syncthreads();
    if (tid < 16) {
        float mm = redm[tid];
#pragma unroll
        for (int o = 8; o > 0; o >>= 1) mm = fmaxf(mm, __shfl_xor_sync(0x0000ffffu, mm, o));
        if (tid == 0) redm[0] = mm;
    }
    __syncthreads();
    float mx = redm[0];

    float e = (tid < cL) ? __expf(sval - mx) : 0.0f;
    float ss = e;
#pragma unroll
    for (int o = 16; o > 0; o >>= 1) ss += __shfl_xor_sync(0xffffffffu, ss, o);
    if (lane == 0) reds[warp] = ss;
    __syncthreads();
    if (tid < 16) {
        float s2 = reds[tid];
#pragma unroll
        for (int o = 8; o > 0; o >>= 1) s2 += __shfl_xor_sync(0x0000ffffu, s2, o);
        if (tid == 0) reds[0] = s2;
    }
    __syncthreads();
    float tot = reds[0];

    if (tid < cL) {
        out[((size_t)b * cL + t) * cL + tid] = sval - mx - __logf(tot);
        ajs[tid] = __fdividef(e, tot);
    }
    __syncthreads();

    // context[j] = sum_l aj[l] * enc_out[b,l,j]; assemble x_cat (bf16)
    float acc = 0.0f;
    const bf16* eo = g_enc_outb + (size_t)b * cL * cH + tid;
#pragma unroll 8
    for (int l = 0; l < cL; l++)
        acc = fmaf(ajs[l], __bfloat162float(eo[(size_t)l * cH]), acc);

    g_xcatb[b * KCAT + tid]      = __float2bfloat16_rn(acc);
    g_xcatb[b * KCAT + cH + tid] = hb[b * cH + tid];
}

// ---------------- host orchestration ----------------
extern "C" void kernel_launch(void* const* d_in, const int* in_sizes, int n_in,
                              void* d_out, int out_size) {
    const int*   xs      = (const int*)d_in[0];
    const int*   argsort = (const int*)d_in[2];
    const float* enc_Wi  = (const float*)d_in[3];
    const float* enc_Wh  = (const float*)d_in[4];
    const float* enc_b   = (const float*)d_in[5];
    const float* dec_Wi  = (const float*)d_in[6];
    const float* dec_Wh  = (const float*)d_in[7];
    const float* dec_b   = (const float*)d_in[8];
    const float* w1      = (const float*)d_in[9];
    const float* w2      = (const float*)d_in[10];
    const float* vt      = (const float*)d_in[11];
    float*       out     = (float*)d_out;

    bf16 *ph0, *ph1, *peo, *pew1, *pxcat, *pWhx, *pcatW, *pw1b, *pw2b;
    float *pq, *pbe, *pbd;
    cudaGetSymbolAddress((void**)&ph0,   g_hb);
    ph1 = ph0 + cB * cH;
    cudaGetSymbolAddress((void**)&pq,    g_q);
    cudaGetSymbolAddress((void**)&peo,   g_enc_outb);
    cudaGetSymbolAddress((void**)&pew1,  g_enc_w1b);
    cudaGetSymbolAddress((void**)&pxcat, g_xcatb);
    cudaGetSymbolAddress((void**)&pWhx,  g_Whx);
    cudaGetSymbolAddress((void**)&pcatW, g_catW);
    cudaGetSymbolAddress((void**)&pw1b,  g_w1b);
    cudaGetSymbolAddress((void**)&pw2b,  g_w2b);
    cudaGetSymbolAddress((void**)&pbe,   g_be);
    cudaGetSymbolAddress((void**)&pbd,   g_bd);

    prep_kernel<<<2080, 1024>>>(xs, argsort, enc_Wi, enc_Wh, enc_b,
                                dec_Wi, dec_Wh, dec_b, w1, w2);

    bf16* hb[2] = {ph0, ph1};
    int cur = 0;

    // ---------------- encoder: 128 steps ----------------
    for (int t = 0; t < cL; t++) {
        gemm_mma<<<dim3(cH4 / BN, cB / BM), 128>>>(
            hb[cur], pWhx, nullptr, nullptr, pbe, xs, hb[cur ^ 1],
            cB, cH4, cH, 1, t);
        cur ^= 1;
    }

    // enc_w1 = enc_out @ w1^T  (bf16 out for attention)
    gemm_mma<<<dim3(cH / BN, (cB * cL) / BM), 128>>>(
        peo, pw1b, nullptr, pew1, nullptr, nullptr, nullptr,
        cB * cL, cH, cH, 3, 0);

    // ---------------- decoder: 128 steps ----------------
    for (int t = 0; t < cL; t++) {
        gemm_mma<<<dim3(cH / BN, cB / BM), 128>>>(
            hb[cur], pw2b, pq, nullptr, nullptr, nullptr, nullptr,
            cB, cH, cH, 0, 0);
        attn_fused<<<cB, 512>>>(vt, t, out, hb[cur]);
        gemm_mma<<<dim3(cH4 / BN, cB / BM), 128>>>(
            pxcat, pcatW, nullptr, nullptr, pbd, nullptr, hb[cur ^ 1],
            cB, cH4, KCAT, 2, t);
        cur ^= 1;
    }
}